// round 14
// baseline (speedup 1.0000x reference)
#include <cuda_runtime.h>

// Problem constants
#define TT     25
#define FF     14
#define HH     24
#define KK     38     // FF + HH fused weight row
#define NSTEPS 13     // fwd needs t=0..12, bwd needs t=24..12
#define BTOT   65536
#define BLK    128
#define EPB    128    // elems per CTA
#define JH     12     // j's per half
#define NCLS   4
#define XS     15     // s_x row stride (odd -> conflict-free)

typedef unsigned long long u64;

__device__ __forceinline__ u64 pack2(float lo, float hi) {
    u64 r; asm("mov.b64 %0, {%1, %2};" : "=l"(r) : "f"(lo), "f"(hi)); return r;
}
__device__ __forceinline__ u64 dup2(float v) {
    u64 r; asm("mov.b64 %0, {%1, %1};" : "=l"(r) : "f"(v)); return r;
}
__device__ __forceinline__ void unpack2(u64 v, float& lo, float& hi) {
    asm("mov.b64 {%0, %1}, %2;" : "=f"(lo), "=f"(hi) : "l"(v));
}
__device__ __forceinline__ void ffma2(u64& d, u64 a, u64 b) {
    asm("fma.rn.f32x2 %0, %1, %2, %0;" : "+l"(d) : "l"(a), "l"(b));
}

__device__ __forceinline__ float ex2f_(float x) {
    float y; asm("ex2.approx.f32 %0, %1;" : "=f"(y) : "f"(x)); return y;
}
__device__ __forceinline__ float rcpf_(float x) {
    float y; asm("rcp.approx.f32 %0, %1;" : "=f"(y) : "f"(x)); return y;
}
__device__ __forceinline__ float sigf_(float x) {
    return rcpf_(1.0f + ex2f_(-1.4426950408889634f * x));
}
// tanh(x) = 2*sigmoid(2x) - 1
__device__ __forceinline__ float tanhf_(float x) {
    float a = ex2f_(-2.8853900817779268f * x);
    float r = rcpf_(1.0f + a);
    return fmaf(2.0f, r, -1.0f);
}

__global__ __launch_bounds__(256)
void init_out_kernel(const float* __restrict__ head_b, float* __restrict__ out)
{
    const int b = blockIdx.x * blockDim.x + threadIdx.x;
    ((float4*)out)[b] = make_float4(head_b[0], head_b[1], head_b[2], head_b[3]);
}

__global__ __launch_bounds__(BLK, 4)
void lstm_kernel(const float* __restrict__ x,
                 const float* __restrict__ wih_f, const float* __restrict__ whh_f,
                 const float* __restrict__ bih_f, const float* __restrict__ bhh_f,
                 const float* __restrict__ wih_b, const float* __restrict__ whh_b,
                 const float* __restrict__ bih_b, const float* __restrict__ bhh_b,
                 const float* __restrict__ head_w, float* __restrict__ out)
{
    __shared__ ulonglong2 s_w[HH * KK];       // 14592 B {(wi,wf),(wg,wo)}
    __shared__ u64 s_bif[HH];                 //   192 B
    __shared__ u64 s_bgo[HH];                 //   192 B
    __shared__ float s_hw[NCLS * HH];         //   384 B
    __shared__ float s_c[BLK * 25];           // 12800 B  c: [thread][jj + elem*12]
    __shared__ float s_h[EPB * 25];           // 12800 B  h single buffer [elem][j]
    __shared__ float s_x[EPB * XS];           //  7680 B  staged x slice [elem][f]

    const int tid  = threadIdx.x;
    const int e    = tid & 63;
    const int half = tid >> 6;
    const int j0   = half * JH;

    const int dir = blockIdx.x & 1;
    const float* wih = dir ? wih_b : wih_f;
    const float* whh = dir ? whh_b : whh_f;
    const float* bih = dir ? bih_b : bih_f;
    const float* bhh = dir ? bhh_b : bhh_f;

    for (int i = tid; i < HH * KK; i += BLK) {
        int j = i / KK, k = i % KK;
        float wi, wf, wg, wo;
        if (k < FF) {
            wi = wih[j * FF + k];
            wf = wih[(j + HH) * FF + k];
            wg = wih[(j + 2 * HH) * FF + k];
            wo = wih[(j + 3 * HH) * FF + k];
        } else {
            int kk = k - FF;
            wi = whh[j * HH + kk];
            wf = whh[(j + HH) * HH + kk];
            wg = whh[(j + 2 * HH) * HH + kk];
            wo = whh[(j + 3 * HH) * HH + kk];
        }
        ulonglong2 w; w.x = pack2(wi, wf); w.y = pack2(wg, wo);
        s_w[i] = w;
    }
    if (tid < HH) {
        int j = tid;
        s_bif[j] = pack2(bih[j] + bhh[j],                   bih[j + HH] + bhh[j + HH]);
        s_bgo[j] = pack2(bih[j + 2 * HH] + bhh[j + 2 * HH], bih[j + 3 * HH] + bhh[j + 3 * HH]);
    }
    if (tid < NCLS * HH) {
        int m = tid / HH, j = tid % HH;
        s_hw[m * HH + j] = head_w[m * (2 * HH) + dir * HH + j];
    }

    const int base = (blockIdx.x >> 1) * EPB;
    const int t0 = dir ? (TT - 1) : 0;
    const int dt = dir ? -1 : 1;

    // zero h buffer (each thread its write-cols) and c
    float* ct = &s_c[tid * 25];
    #pragma unroll
    for (int jj = 0; jj < JH; ++jj) {
        s_h[e * 25 + j0 + jj]        = 0.f;
        s_h[(64 + e) * 25 + j0 + jj] = 0.f;
        ct[jj] = 0.f; ct[JH + jj] = 0.f;
    }

    // Prefetch pipeline: thread tid stages slots idx = tid + i*BLK (i<7);
    // slot -> (elem ee = idx/7, pair f2 = idx%7).
    float2 px[7];
    {
        const int t = t0;
        #pragma unroll
        for (int i = 0; i < 7; ++i) {
            int idx = tid + i * BLK;
            int ee = idx / 7, f2 = idx - ee * 7;
            px[i] = __ldg((const float2*)(x + (size_t)(base + ee) * (TT * FF) + t * FF) + f2);
        }
        #pragma unroll
        for (int i = 0; i < 7; ++i) {
            int idx = tid + i * BLK;
            int ee = idx / 7, f2 = idx - ee * 7;
            s_x[ee * XS + 2 * f2]     = px[i].x;
            s_x[ee * XS + 2 * f2 + 1] = px[i].y;
        }
    }
    __syncthreads();

    for (int s = 0; s < NSTEPS; ++s) {
        // issue next step's x loads EARLY (latency hidden behind the j-loop)
        if (s + 1 < NSTEPS) {
            const int t = t0 + dt * (s + 1);
            #pragma unroll
            for (int i = 0; i < 7; ++i) {
                int idx = tid + i * BLK;
                int ee = idx / 7, f2 = idx - ee * 7;
                px[i] = __ldg((const float2*)(x + (size_t)(base + ee) * (TT * FF) + t * FF) + f2);
            }
        }

        // ---- read phase: x and h(s-1) into registers ----
        float xv0[FF], xv1[FF], hr0[HH], hr1[HH];
        const float* xp0 = &s_x[e * XS];
        const float* xp1 = &s_x[(64 + e) * XS];
        const float* hp0 = &s_h[e * 25];
        const float* hp1 = &s_h[(64 + e) * 25];
        #pragma unroll
        for (int k = 0; k < FF; ++k) { xv0[k] = xp0[k]; xv1[k] = xp1[k]; }
        #pragma unroll
        for (int k = 0; k < HH; ++k) { hr0[k] = hp0[k]; hr1[k] = hp1[k]; }
        __syncthreads();            // BAR1: all reads done before overwrites

        float* wr0 = &s_h[e * 25];
        float* wr1 = &s_h[(64 + e) * 25];

        #pragma unroll 2
        for (int jj = 0; jj < JH; ++jj) {
            const int j = j0 + jj;
            u64 aif0 = s_bif[j], ago0 = s_bgo[j];
            u64 aif1 = aif0,     ago1 = ago0;
            const ulonglong2* wp = &s_w[j * KK];
            #pragma unroll
            for (int k = 0; k < FF; ++k) {
                ulonglong2 w = wp[k];                    // broadcast LDS.128
                u64 d0 = dup2(xv0[k]);
                u64 d1 = dup2(xv1[k]);
                ffma2(aif0, d0, w.x); ffma2(ago0, d0, w.y);
                ffma2(aif1, d1, w.x); ffma2(ago1, d1, w.y);
            }
            #pragma unroll
            for (int k = 0; k < HH; ++k) {
                ulonglong2 w = wp[FF + k];
                u64 d0 = dup2(hr0[k]);
                u64 d1 = dup2(hr1[k]);
                ffma2(aif0, d0, w.x); ffma2(ago0, d0, w.y);
                ffma2(aif1, d1, w.x); ffma2(ago1, d1, w.y);
            }
            {
                float ai, af, ag, ao;
                unpack2(aif0, ai, af); unpack2(ago0, ag, ao);
                float ii = sigf_(ai), ff = sigf_(af), oo = sigf_(ao), gg = tanhf_(ag);
                float cn = ff * ct[jj] + ii * gg;
                ct[jj] = cn;
                wr0[j] = oo * tanhf_(cn);
            }
            {
                float ai, af, ag, ao;
                unpack2(aif1, ai, af); unpack2(ago1, ag, ao);
                float ii = sigf_(ai), ff = sigf_(af), oo = sigf_(ao), gg = tanhf_(ag);
                float cn = ff * ct[JH + jj] + ii * gg;
                ct[JH + jj] = cn;
                wr1[j] = oo * tanhf_(cn);
            }
        }

        // store prefetched x(s+1) (data already resident in registers)
        if (s + 1 < NSTEPS) {
            #pragma unroll
            for (int i = 0; i < 7; ++i) {
                int idx = tid + i * BLK;
                int ee = idx / 7, f2 = idx - ee * 7;
                s_x[ee * XS + 2 * f2]     = px[i].x;
                s_x[ee * XS + 2 * f2 + 1] = px[i].y;
            }
        }
        __syncthreads();            // BAR2: h(s) + x(s+1) visible
    }

    // Head: thread tid handles elem row tid (full h in s_h)
    const float* hf = &s_h[tid * 25];
    float p0 = 0.f, p1 = 0.f, p2 = 0.f, p3 = 0.f;
    #pragma unroll
    for (int j = 0; j < HH; ++j) {
        float v = hf[j];
        p0 += v * s_hw[j];
        p1 += v * s_hw[HH + j];
        p2 += v * s_hw[2 * HH + j];
        p3 += v * s_hw[3 * HH + j];
    }
    float* ob = out + (size_t)(base + tid) * NCLS;
    atomicAdd(ob + 0, p0); atomicAdd(ob + 1, p1);
    atomicAdd(ob + 2, p2); atomicAdd(ob + 3, p3);
}

extern "C" void kernel_launch(void* const* d_in, const int* in_sizes, int n_in,
                              void* d_out, int out_size)
{
    const float* x      = (const float*)d_in[0];
    const float* wih_f  = (const float*)d_in[1];
    const float* whh_f  = (const float*)d_in[2];
    const float* bih_f  = (const float*)d_in[3];
    const float* bhh_f  = (const float*)d_in[4];
    const float* wih_b  = (const float*)d_in[5];
    const float* whh_b  = (const float*)d_in[6];
    const float* bih_b  = (const float*)d_in[7];
    const float* bhh_b  = (const float*)d_in[8];
    const float* head_w = (const float*)d_in[9];
    const float* head_b = (const float*)d_in[10];
    float* out = (float*)d_out;

    init_out_kernel<<<BTOT / 256, 256>>>(head_b, out);
    lstm_kernel<<<(BTOT / EPB) * 2, BLK>>>(x, wih_f, whh_f, bih_f, bhh_f,
                                           wih_b, whh_b, bih_b, bhh_b,
                                           head_w, out);
}